// round 2
// baseline (speedup 1.0000x reference)
#include <cuda_runtime.h>
#include <cstdint>

#define CIN  64
#define COUT 64
#define KTAP 9
#define EPS_BN 1e-4f
#define LEAK 0.333f

#define MAX_N 1000000
// scratch: y buffer [N, 64] fp32
__device__ float g_y[(size_t)MAX_N * COUT];
__device__ float g_sum[COUT];
__device__ float g_ssq[COUT];
__device__ float g_scale[COUT];
__device__ float g_bias[COUT];
__device__ int   g_valid_u8;   // 1 if valid[] is 1-byte elements, 0 if 4-byte

// ---------- packed f32x2 helpers (FFMA2 only reachable via PTX) ----------
__device__ __forceinline__ unsigned long long pk2(float a, float b) {
    unsigned long long r;
    asm("mov.b64 %0, {%1, %2};" : "=l"(r) : "f"(a), "f"(b));
    return r;
}
__device__ __forceinline__ void fma2(unsigned long long& d,
                                     unsigned long long a,
                                     unsigned long long b) {
    asm("fma.rn.f32x2 %0, %1, %2, %0;" : "+l"(d) : "l"(a), "l"(b));
}
__device__ __forceinline__ float2 upk(unsigned long long v) {
    float x, y;
    asm("mov.b64 {%0, %1}, %2;" : "=f"(x), "=f"(y) : "l"(v));
    return make_float2(x, y);
}

// ---------------- kernel 0: zero stats + detect valid dtype ----------------
// 4-byte bool elements (int32 0/1 or float32 0.0/1.0) -> every 32-bit word is
// 0x0, 0x1, or 0x3F800000. 1-byte packed bools -> words are 0x00/0x01 byte
// combos (e.g. 0x00010001), which never match the 4-byte set at 70% density.
__global__ void init_kernel(const unsigned int* __restrict__ vwords, int nwords) {
    __shared__ int s_flag;
    int t = threadIdx.x;
    if (t == 0) s_flag = 0;
    if (t < COUT) { g_sum[t] = 0.0f; g_ssq[t] = 0.0f; }
    __syncthreads();
    int local = 0;
    for (int i = t; i < nwords; i += blockDim.x) {
        unsigned int w = vwords[i];
        if (w != 0u && w != 1u && w != 0x3F800000u) local = 1;
    }
    if (local) atomicOr(&s_flag, 1);
    __syncthreads();
    if (t == 0) g_valid_u8 = s_flag;
}

// ---------------- kernel 1: sparse conv ----------------
// block: 256 threads (8 warps). Each warp handles 8 rows per tile (64 rows/block/tile).
// SMEM: full W [9][64][64] (147456 B) + gather staging [8 warps][8 rows][68] (17408 B)
#define GPAD 68
#define SMEM_W_FLOATS (KTAP * CIN * COUT)
#define SMEM_G_FLOATS (8 * 8 * GPAD)
#define CONV_SMEM_BYTES ((SMEM_W_FLOATS + SMEM_G_FLOATS) * 4)

__global__ void __launch_bounds__(256, 1)
conv_kernel(const float* __restrict__ feats,
            const float* __restrict__ W,
            const int* __restrict__ nidx,
            const void* __restrict__ validp,
            int N) {
    extern __shared__ float smem[];
    float* W_s = smem;                       // [9][64][64]
    float* G_s = smem + SMEM_W_FLOATS;       // [8][8][GPAD]
    __shared__ float s_sum[COUT];
    __shared__ float s_ssq[COUT];

    const int tid  = threadIdx.x;
    const int warp = tid >> 5;
    const int lane = tid & 31;
    const int valid_u8 = g_valid_u8;
    const int* __restrict__ valid32 = (const int*)validp;
    const unsigned char* __restrict__ valid8 = (const unsigned char*)validp;

    // load full W into shared (layout identical to global)
    {
        const float4* src = (const float4*)W;
        float4* dst = (float4*)W_s;
        for (int i = tid; i < SMEM_W_FLOATS / 4; i += blockDim.x) dst[i] = src[i];
    }
    if (tid < COUT) { s_sum[tid] = 0.0f; s_ssq[tid] = 0.0f; }
    __syncthreads();

    float* gw = G_s + warp * (8 * GPAD);

    const int colg = lane & 15;     // 16 column groups of 4
    const int rowg = lane >> 4;     // 2 row groups of 4
    const int cb   = colg * 4;      // output column base
    const int srow = lane >> 2;     // staging: row this lane loads (0..7)
    const int ssub = lane & 3;      // staging: which quarter of 64 floats

    float csum0 = 0.f, csum1 = 0.f, csum2 = 0.f, csum3 = 0.f;
    float cssq0 = 0.f, cssq1 = 0.f, cssq2 = 0.f, cssq3 = 0.f;

    const int ntiles = (N + 63) / 64;

    for (int tile = blockIdx.x; tile < ntiles; tile += gridDim.x) {
        const int rbase = tile * 64 + warp * 8;

        unsigned long long acc[4][2];
        #pragma unroll
        for (int rr = 0; rr < 4; rr++) { acc[rr][0] = 0ull; acc[rr][1] = 0ull; }

        for (int k = 0; k < KTAP; k++) {
            // ---- stage gathered features for this warp's 8 rows ----
            const int r = rbase + srow;
            float4 z = make_float4(0.f, 0.f, 0.f, 0.f);
            if (r < N) {
                const int vidx = r * KTAP + k;
                const int nb   = nidx[vidx];
                const bool v   = valid_u8 ? (valid8[vidx] != 0)
                                          : (valid32[vidx] != 0);
                const float4* src = (const float4*)(feats + (size_t)nb * CIN);
                #pragma unroll
                for (int j = 0; j < 4; j++) {
                    const int e4 = j * 4 + ssub;           // float4 index 0..15
                    float4 val = v ? src[e4] : z;
                    *(float4*)(gw + srow * GPAD + e4 * 4) = val;
                }
            } else {
                #pragma unroll
                for (int j = 0; j < 4; j++) {
                    const int e4 = j * 4 + ssub;
                    *(float4*)(gw + srow * GPAD + e4 * 4) = z;
                }
            }
            __syncwarp();

            // ---- compute: 4 rows x 4 cols per lane via packed f32x2 FMA ----
            const float* wk = W_s + k * (CIN * COUT) + cb;
            const float* g0 = gw + (rowg * 4) * GPAD;
            #pragma unroll 16
            for (int ci = 0; ci < CIN; ci++) {
                float4 w4 = *(const float4*)(wk + ci * COUT);
                unsigned long long wlo = pk2(w4.x, w4.y);
                unsigned long long whi = pk2(w4.z, w4.w);
                #pragma unroll
                for (int rr = 0; rr < 4; rr++) {
                    float gv = g0[rr * GPAD + ci];
                    unsigned long long gg = pk2(gv, gv);
                    fma2(acc[rr][0], gg, wlo);
                    fma2(acc[rr][1], gg, whi);
                }
            }
            __syncwarp();   // protect staging buffer before next tap overwrites
        }

        // ---- write y + accumulate BN partial sums ----
        #pragma unroll
        for (int rr = 0; rr < 4; rr++) {
            const int r = rbase + rowg * 4 + rr;
            if (r < N) {
                float2 p0 = upk(acc[rr][0]);
                float2 p1 = upk(acc[rr][1]);
                float4 o = make_float4(p0.x, p0.y, p1.x, p1.y);
                *(float4*)(g_y + (size_t)r * COUT + cb) = o;
                csum0 += o.x; csum1 += o.y; csum2 += o.z; csum3 += o.w;
                cssq0 += o.x * o.x; cssq1 += o.y * o.y;
                cssq2 += o.z * o.z; cssq3 += o.w * o.w;
            }
        }
    }

    // ---- block-level stats reduction, then one global atomic per column ----
    atomicAdd(&s_sum[cb + 0], csum0); atomicAdd(&s_ssq[cb + 0], cssq0);
    atomicAdd(&s_sum[cb + 1], csum1); atomicAdd(&s_ssq[cb + 1], cssq1);
    atomicAdd(&s_sum[cb + 2], csum2); atomicAdd(&s_ssq[cb + 2], cssq2);
    atomicAdd(&s_sum[cb + 3], csum3); atomicAdd(&s_ssq[cb + 3], cssq3);
    __syncthreads();
    if (tid < COUT) {
        atomicAdd(&g_sum[tid], s_sum[tid]);
        atomicAdd(&g_ssq[tid], s_ssq[tid]);
    }
}

// ---------------- kernel 2: finalize BN scale/bias ----------------
__global__ void bn_finalize_kernel(const float* __restrict__ gamma,
                                   const float* __restrict__ beta,
                                   int N) {
    int c = threadIdx.x;
    if (c < COUT) {
        float inv_n = 1.0f / (float)N;
        float mean = g_sum[c] * inv_n;
        float var  = g_ssq[c] * inv_n - mean * mean;
        float sc   = gamma[c] * rsqrtf(var + EPS_BN);
        g_scale[c] = sc;
        g_bias[c]  = beta[c] - mean * sc;
    }
}

// ---------------- kernel 3: apply BN + LeakyReLU ----------------
__global__ void __launch_bounds__(256)
apply_kernel(float* __restrict__ out, int total4) {
    __shared__ float ss[COUT];
    __shared__ float sb[COUT];
    if (threadIdx.x < COUT) {
        ss[threadIdx.x] = g_scale[threadIdx.x];
        sb[threadIdx.x] = g_bias[threadIdx.x];
    }
    __syncthreads();

    const float4* y4 = (const float4*)g_y;
    float4* o4 = (float4*)out;
    for (int i = blockIdx.x * blockDim.x + threadIdx.x; i < total4;
         i += gridDim.x * blockDim.x) {
        float4 y = y4[i];
        int c = (i & 15) * 4;       // 16 float4 per row of 64
        float4 o;
        o.x = y.x * ss[c + 0] + sb[c + 0];
        o.y = y.y * ss[c + 1] + sb[c + 1];
        o.z = y.z * ss[c + 2] + sb[c + 2];
        o.w = y.w * ss[c + 3] + sb[c + 3];
        o.x = (o.x >= 0.f) ? o.x : LEAK * o.x;
        o.y = (o.y >= 0.f) ? o.y : LEAK * o.y;
        o.z = (o.z >= 0.f) ? o.z : LEAK * o.z;
        o.w = (o.w >= 0.f) ? o.w : LEAK * o.w;
        o4[i] = o;
    }
}

// ---------------- launch ----------------
extern "C" void kernel_launch(void* const* d_in, const int* in_sizes, int n_in,
                              void* d_out, int out_size) {
    const float* feats = (const float*)d_in[0];
    const float* W     = (const float*)d_in[1];
    const float* gamma = (const float*)d_in[2];
    const float* beta  = (const float*)d_in[3];
    const int*   nidx  = (const int*)d_in[4];
    const void*  valid = (const void*)d_in[5];

    const int N = in_sizes[0] / CIN;

    cudaFuncSetAttribute(conv_kernel,
                         cudaFuncAttributeMaxDynamicSharedMemorySize,
                         CONV_SMEM_BYTES);

    // scan first 4096 words of valid[] (exists under either dtype: >=9e6 elems)
    init_kernel<<<1, 256>>>((const unsigned int*)valid, 4096);

    int conv_grid = 1184;  // ~8 tiles/SM grid-stride; W loaded once per block
    int ntiles = (N + 63) / 64;
    if (conv_grid > ntiles) conv_grid = ntiles;
    conv_kernel<<<conv_grid, 256, CONV_SMEM_BYTES>>>(feats, W, nidx, valid, N);

    bn_finalize_kernel<<<1, 64>>>(gamma, beta, N);

    int total4 = (N * COUT) / 4;
    apply_kernel<<<8192, 256>>>((float*)d_out, total4);
}

// round 7
// speedup vs baseline: 1.0889x; 1.0889x over previous
#include <cuda_runtime.h>
#include <cuda_bf16.h>
#include <cstdint>

#define CIN  64
#define COUT 64
#define KTAP 9
#define EPS_BN 1e-4f
#define LEAK 0.333f
#define MAX_N 1000000
#define TILE_M 128

// ---------------- global scratch ----------------
__device__ float g_y[(size_t)MAX_N * COUT];
__device__ float g_sum[COUT];
__device__ float g_ssq[COUT];
__device__ float g_scale[COUT];
__device__ float g_bias[COUT];
__device__ int   g_valid_u8;
// W transposed+split+swizzled: [tap][hi/lo] planes of [64 n-rows x 128B]
__device__ unsigned char g_wt[KTAP * 2 * 8192];

#define SWZ128(o) ((o) ^ (((o) >> 3) & 0x70))

// ---------------- PTX helpers (portable sm_80-level only) ----------------
__device__ __forceinline__ uint32_t smem_u32(const void* p) {
    uint32_t a;
    asm("{ .reg .u64 t; cvta.to.shared.u64 t, %1; cvt.u32.u64 %0, t; }"
        : "=r"(a) : "l"(p));
    return a;
}
__device__ __forceinline__ void ldsm_x4(uint32_t addr, uint32_t& r0, uint32_t& r1,
                                        uint32_t& r2, uint32_t& r3) {
    asm volatile("ldmatrix.sync.aligned.m8n8.x4.shared.b16 {%0,%1,%2,%3}, [%4];"
                 : "=r"(r0), "=r"(r1), "=r"(r2), "=r"(r3) : "r"(addr));
}
__device__ __forceinline__ void ldsm_x2(uint32_t addr, uint32_t& r0, uint32_t& r1) {
    asm volatile("ldmatrix.sync.aligned.m8n8.x2.shared.b16 {%0,%1}, [%2];"
                 : "=r"(r0), "=r"(r1) : "r"(addr));
}
__device__ __forceinline__ void mma_bf16(float* c, const uint32_t* a,
                                         const uint32_t* b) {
    asm volatile(
        "mma.sync.aligned.m16n8k16.row.col.f32.bf16.bf16.f32 "
        "{%0,%1,%2,%3}, {%4,%5,%6,%7}, {%8,%9}, {%0,%1,%2,%3};"
        : "+f"(c[0]), "+f"(c[1]), "+f"(c[2]), "+f"(c[3])
        : "r"(a[0]), "r"(a[1]), "r"(a[2]), "r"(a[3]), "r"(b[0]), "r"(b[1]));
}
__device__ __forceinline__ void hilo2(float x, float y, uint32_t& h, uint32_t& l) {
    __nv_bfloat16 hx = __float2bfloat16_rn(x);
    __nv_bfloat16 hy = __float2bfloat16_rn(y);
    __nv_bfloat162 hp; hp.x = hx; hp.y = hy;
    h = reinterpret_cast<uint32_t&>(hp);
    __nv_bfloat16 lx = __float2bfloat16_rn(x - __bfloat162float(hx));
    __nv_bfloat16 ly = __float2bfloat16_rn(y - __bfloat162float(hy));
    __nv_bfloat162 lp; lp.x = lx; lp.y = ly;
    l = reinterpret_cast<uint32_t&>(lp);
}

// ---------------- kernel: init (zero stats + detect valid dtype) ----------------
__global__ void init_kernel(const unsigned int* __restrict__ vwords, int nwords) {
    __shared__ int s_flag;
    int t = threadIdx.x;
    if (t == 0) s_flag = 0;
    if (t < COUT) { g_sum[t] = 0.0f; g_ssq[t] = 0.0f; }
    __syncthreads();
    int local = 0;
    for (int i = t; i < nwords; i += blockDim.x) {
        unsigned int w = vwords[i];
        if (w != 0u && w != 1u && w != 0x3F800000u) local = 1;
    }
    if (local) atomicOr(&s_flag, 1);
    __syncthreads();
    if (t == 0) g_valid_u8 = s_flag;
}

// ---------------- kernel: prep W (transpose + hi/lo split + swizzle) ----------------
// plane layout: [n row 0..63][k byte 0..127] bf16, SW128-swizzled
__global__ void prep_w_kernel(const float* __restrict__ W) {
    int i = blockIdx.x * blockDim.x + threadIdx.x;
    if (i >= KTAP * CIN * COUT) return;
    int t = i / (CIN * COUT);
    int rem = i % (CIN * COUT);
    int ci = rem / COUT;
    int n = rem % COUT;
    float x = W[i];                     // W[t][ci][n]
    __nv_bfloat16 h = __float2bfloat16_rn(x);
    __nv_bfloat16 l = __float2bfloat16_rn(x - __bfloat162float(h));
    uint32_t off = SWZ128((uint32_t)(n * 128 + ci * 2));
    *(unsigned short*)(g_wt + (t * 2 + 0) * 8192 + off) =
        reinterpret_cast<unsigned short&>(h);
    *(unsigned short*)(g_wt + (t * 2 + 1) * 8192 + off) =
        reinterpret_cast<unsigned short&>(l);
}

// ---------------- kernel: conv (mma.sync bf16 split) ----------------
#define W_BYTES   (KTAP * 2 * 8192)            // 147456
#define SMEM_A    W_BYTES
#define APLANE    16384                         // one [128x64] bf16 plane
#define ABUF      (2 * APLANE)                  // hi + lo
#define CONV_SMEM (SMEM_A + 2 * ABUF)           // 212992

__global__ void __launch_bounds__(256, 1)
conv_kernel(const float* __restrict__ feats,
            const int* __restrict__ nidx,
            const void* __restrict__ validp,
            int N, int ntiles) {
    extern __shared__ char smem[];
    const uint32_t sb = smem_u32(smem);
    __shared__ float s_sum[COUT];
    __shared__ float s_ssq[COUT];

    const int tid = threadIdx.x, warp = tid >> 5, lane = tid & 31;
    const int vu8 = g_valid_u8;
    const int* __restrict__ v32 = (const int*)validp;
    const unsigned char* __restrict__ v8 = (const unsigned char*)validp;

    if (tid < COUT) { s_sum[tid] = 0.0f; s_ssq[tid] = 0.0f; }

    // copy pre-swizzled W planes into SMEM (visibility covered by first tap sync)
    {
        const uint4* s = (const uint4*)g_wt;
        uint4* d = (uint4*)smem;
        for (int i = tid; i < W_BYTES / 16; i += 256) d[i] = s[i];
    }

    // warp tiling: 4 m-slices x 2 n-slices of 32x32
    const int warp_m = warp & 3;
    const int warp_n = warp >> 2;
    // gather mapping: 2 threads per row
    const int rit  = tid >> 1;
    const int half = tid & 1;
    const uint32_t stbase = (uint32_t)(rit * 128 + half * 64);
    // ldmatrix lane-constant components
    const uint32_t rowA = (uint32_t)(warp_m * 32 + ((lane >> 3) & 1) * 8 + (lane & 7));
    const uint32_t kbA  = (uint32_t)((lane >> 4) * 16);
    const uint32_t rowW = (uint32_t)(warp_n * 32 + (lane & 7));
    const uint32_t kbW  = (uint32_t)(((lane >> 3) & 1) * 16);

    // gather state (one tap ahead)
    int gtile = blockIdx.x, gtap = 0;
    float4 f[8];
    auto do_gather = [&]() {
        const int r = gtile * TILE_M + rit;
        bool live = false;
        const float4* src = nullptr;
        if (r < N) {
            const int vidx = r * KTAP + gtap;
            const bool v = vu8 ? (v8[vidx] != 0) : (v32[vidx] != 0);
            if (v) {
                live = true;
                src = (const float4*)(feats + (size_t)nidx[vidx] * CIN + half * 32);
            }
        }
        if (live) {
            #pragma unroll
            for (int j = 0; j < 8; j++) f[j] = src[j];
        } else {
            #pragma unroll
            for (int j = 0; j < 8; j++) f[j] = make_float4(0.f, 0.f, 0.f, 0.f);
        }
    };
    if (gtile < ntiles) do_gather();

    float st_sum[8], st_ssq[8];
    #pragma unroll
    for (int i = 0; i < 8; i++) { st_sum[i] = 0.f; st_ssq[i] = 0.f; }

    int parity = 0;

    for (int tile = blockIdx.x; tile < ntiles; tile += gridDim.x) {
        float C[2][4][4];
        #pragma unroll
        for (int mb = 0; mb < 2; mb++)
            #pragma unroll
            for (int nb = 0; nb < 4; nb++)
                #pragma unroll
                for (int q = 0; q < 4; q++) C[mb][nb][q] = 0.f;

        for (int tap = 0; tap < KTAP; tap++) {
            // ---- store staged gather (bf16 hi/lo, swizzled) ----
            char* ahi = smem + SMEM_A + parity * ABUF;
            char* alo = ahi + APLANE;
            #pragma unroll
            for (int j = 0; j < 4; j++) {
                float4 a = f[2 * j], c4 = f[2 * j + 1];
                uint4 hv, lv;
                hilo2(a.x, a.y, hv.x, lv.x);
                hilo2(a.z, a.w, hv.y, lv.y);
                hilo2(c4.x, c4.y, hv.z, lv.z);
                hilo2(c4.z, c4.w, hv.w, lv.w);
                const uint32_t so = SWZ128(stbase + j * 16);
                *(uint4*)(ahi + so) = hv;
                *(uint4*)(alo + so) = lv;
            }
            __syncthreads();

            // ---- issue next gather (LDGs overlap the MMA block below) ----
            if (++gtap == KTAP) { gtap = 0; gtile += gridDim.x; }
            if (gtile < ntiles) do_gather();

            // ---- MMA: 3 combos per (mb, nb, kstep) ----
            const uint32_t aHiB = sb + SMEM_A + parity * ABUF;
            const uint32_t aLoB = aHiB + APLANE;
            const uint32_t wHiB = sb + (uint32_t)((tap * 2 + 0) * 8192);
            const uint32_t wLoB = wHiB + 8192;
            #pragma unroll
            for (int ks = 0; ks < 4; ks++) {
                uint32_t Wh[4][2], Wl[4][2];
                #pragma unroll
                for (int nb = 0; nb < 4; nb++) {
                    const uint32_t wo = SWZ128((rowW + nb * 8) * 128 + ks * 32 + kbW);
                    ldsm_x2(wHiB + wo, Wh[nb][0], Wh[nb][1]);
                    ldsm_x2(wLoB + wo, Wl[nb][0], Wl[nb][1]);
                }
                uint32_t Ah[2][4], Al[2][4];
                #pragma unroll
                for (int mb = 0; mb < 2; mb++) {
                    const uint32_t ao = SWZ128((rowA + mb * 16) * 128 + ks * 32 + kbA);
                    ldsm_x4(aHiB + ao, Ah[mb][0], Ah[mb][1], Ah[mb][2], Ah[mb][3]);
                    ldsm_x4(aLoB + ao, Al[mb][0], Al[mb][1], Al[mb][2], Al[mb][3]);
                }
                #pragma unroll
                for (int mb = 0; mb < 2; mb++)
                    #pragma unroll
                    for (int nb = 0; nb < 4; nb++) {
                        mma_bf16(C[mb][nb], Ah[mb], Wh[nb]);
                        mma_bf16(C[mb][nb], Ah[mb], Wl[nb]);
                        mma_bf16(C[mb][nb], Al[mb], Wh[nb]);
                    }
            }
            parity ^= 1;
        }

        // ---- epilogue: store y, accumulate BN stats in regs ----
        {
            const int r0 = tile * TILE_M + warp_m * 32 + (lane >> 2);
            const int cbase = warp_n * 32 + (lane & 3) * 2;
            #pragma unroll
            for (int mb = 0; mb < 2; mb++) {
                const int ra = r0 + mb * 16;
                const int rb = ra + 8;
                #pragma unroll
                for (int nb = 0; nb < 4; nb++) {
                    const int c = cbase + nb * 8;
                    if (ra < N)
                        *(float2*)(g_y + (size_t)ra * COUT + c) =
                            make_float2(C[mb][nb][0], C[mb][nb][1]);
                    if (rb < N)
                        *(float2*)(g_y + (size_t)rb * COUT + c) =
                            make_float2(C[mb][nb][2], C[mb][nb][3]);
                    // rows >= N contributed zeros (gather zero-fill) -> no guard
                    st_sum[nb * 2 + 0] += C[mb][nb][0] + C[mb][nb][2];
                    st_sum[nb * 2 + 1] += C[mb][nb][1] + C[mb][nb][3];
                    st_ssq[nb * 2 + 0] += C[mb][nb][0] * C[mb][nb][0] +
                                          C[mb][nb][2] * C[mb][nb][2];
                    st_ssq[nb * 2 + 1] += C[mb][nb][1] * C[mb][nb][1] +
                                          C[mb][nb][3] * C[mb][nb][3];
                }
            }
        }
    }

    // ---- stats: regs -> smem -> global ----
    __syncthreads();
    {
        const int cbase = warp_n * 32 + (lane & 3) * 2;
        #pragma unroll
        for (int nb = 0; nb < 4; nb++) {
            atomicAdd(&s_sum[cbase + nb * 8 + 0], st_sum[nb * 2 + 0]);
            atomicAdd(&s_sum[cbase + nb * 8 + 1], st_sum[nb * 2 + 1]);
            atomicAdd(&s_ssq[cbase + nb * 8 + 0], st_ssq[nb * 2 + 0]);
            atomicAdd(&s_ssq[cbase + nb * 8 + 1], st_ssq[nb * 2 + 1]);
        }
    }
    __syncthreads();
    if (tid < COUT) {
        atomicAdd(&g_sum[tid], s_sum[tid]);
        atomicAdd(&g_ssq[tid], s_ssq[tid]);
    }
}

// ---------------- kernel: finalize BN scale/bias ----------------
__global__ void bn_finalize_kernel(const float* __restrict__ gamma,
                                   const float* __restrict__ beta, int N) {
    int c = threadIdx.x;
    if (c < COUT) {
        float inv_n = 1.0f / (float)N;
        float mean = g_sum[c] * inv_n;
        float var = g_ssq[c] * inv_n - mean * mean;
        float sc = gamma[c] * rsqrtf(var + EPS_BN);
        g_scale[c] = sc;
        g_bias[c] = beta[c] - mean * sc;
    }
}

// ---------------- kernel: apply BN + LeakyReLU ----------------
__global__ void __launch_bounds__(256)
apply_kernel(float* __restrict__ out, int total4) {
    __shared__ float ss[COUT];
    __shared__ float sb_[COUT];
    if (threadIdx.x < COUT) {
        ss[threadIdx.x] = g_scale[threadIdx.x];
        sb_[threadIdx.x] = g_bias[threadIdx.x];
    }
    __syncthreads();
    const float4* y4 = (const float4*)g_y;
    float4* o4 = (float4*)out;
    for (int i = blockIdx.x * blockDim.x + threadIdx.x; i < total4;
         i += gridDim.x * blockDim.x) {
        float4 y = y4[i];
        int c = (i & 15) * 4;
        float4 o;
        o.x = y.x * ss[c + 0] + sb_[c + 0];
        o.y = y.y * ss[c + 1] + sb_[c + 1];
        o.z = y.z * ss[c + 2] + sb_[c + 2];
        o.w = y.w * ss[c + 3] + sb_[c + 3];
        o.x = (o.x >= 0.f) ? o.x : LEAK * o.x;
        o.y = (o.y >= 0.f) ? o.y : LEAK * o.y;
        o.z = (o.z >= 0.f) ? o.z : LEAK * o.z;
        o.w = (o.w >= 0.f) ? o.w : LEAK * o.w;
        o4[i] = o;
    }
}

// ---------------- launch ----------------
extern "C" void kernel_launch(void* const* d_in, const int* in_sizes, int n_in,
                              void* d_out, int out_size) {
    const float* feats = (const float*)d_in[0];
    const float* W     = (const float*)d_in[1];
    const float* gamma = (const float*)d_in[2];
    const float* beta  = (const float*)d_in[3];
    const int*   nidx  = (const int*)d_in[4];
    const void*  valid = (const void*)d_in[5];

    const int N = in_sizes[0] / CIN;
    const int ntiles = (N + TILE_M - 1) / TILE_M;

    cudaFuncSetAttribute(conv_kernel,
                         cudaFuncAttributeMaxDynamicSharedMemorySize, CONV_SMEM);

    init_kernel<<<1, 256>>>((const unsigned int*)valid, 4096);
    prep_w_kernel<<<(KTAP * CIN * COUT + 255) / 256, 256>>>(W);

    int grid = 152;
    if (grid > ntiles) grid = ntiles;
    conv_kernel<<<grid, 256, CONV_SMEM>>>(feats, nidx, valid, N, ntiles);

    bn_finalize_kernel<<<1, 64>>>(gamma, beta, N);

    const int total4 = (N * COUT) / 4;
    apply_kernel<<<8192, 256>>>((float*)d_out, total4);
}

// round 8
// speedup vs baseline: 1.6452x; 1.5109x over previous
#include <cuda_runtime.h>
#include <cuda_bf16.h>
#include <cstdint>

#define CIN  64
#define COUT 64
#define KTAP 9
#define EPS_BN 1e-4f
#define LEAK 0.333f
#define MAX_N 1000000
#define TILE_M 128

// ---------------- global scratch ----------------
__device__ float g_y[(size_t)MAX_N * COUT];
__device__ float g_sum[COUT];
__device__ float g_ssq[COUT];
__device__ float g_scale[COUT];
__device__ float g_bias[COUT];
__device__ int   g_valid_u8;
// W as tf32, layout [tap][ks][n][p*2+e] : k = ks*8 + e*4 + p
__device__ uint32_t g_wtf[KTAP * 4096];

// ---------------- PTX helpers (portable sm_80-level only) ----------------
__device__ __forceinline__ uint32_t f2tf32(float x) {
    uint32_t u;
    asm("cvt.rna.tf32.f32 %0, %1;" : "=r"(u) : "f"(x));
    return u;
}
__device__ __forceinline__ void mma_tf32(float* c, uint32_t a0, uint32_t a1,
                                         uint32_t a2, uint32_t a3,
                                         uint32_t b0, uint32_t b1) {
    asm volatile(
        "mma.sync.aligned.m16n8k8.row.col.f32.tf32.tf32.f32 "
        "{%0,%1,%2,%3}, {%4,%5,%6,%7}, {%8,%9}, {%0,%1,%2,%3};"
        : "+f"(c[0]), "+f"(c[1]), "+f"(c[2]), "+f"(c[3])
        : "r"(a0), "r"(a1), "r"(a2), "r"(a3), "r"(b0), "r"(b1));
}

// ---------------- kernel: init (zero stats + detect valid dtype) ----------------
__global__ void init_kernel(const unsigned int* __restrict__ vwords, int nwords) {
    __shared__ int s_flag;
    int t = threadIdx.x;
    if (t == 0) s_flag = 0;
    if (t < COUT) { g_sum[t] = 0.0f; g_ssq[t] = 0.0f; }
    __syncthreads();
    int local = 0;
    for (int i = t; i < nwords; i += blockDim.x) {
        unsigned int w = vwords[i];
        if (w != 0u && w != 1u && w != 0x3F800000u) local = 1;
    }
    if (local) atomicOr(&s_flag, 1);
    __syncthreads();
    if (t == 0) g_valid_u8 = s_flag;
}

// ---------------- kernel: prep W (transpose + tf32 round + k-pair layout) ----------------
__global__ void prep_w_kernel(const float* __restrict__ W) {
    int i = blockIdx.x * blockDim.x + threadIdx.x;
    if (i >= KTAP * CIN * COUT) return;
    int t = i / (CIN * COUT);
    int rem = i % (CIN * COUT);
    int k = rem / COUT;           // ci
    int n = rem % COUT;
    int ks = k >> 3, r = k & 7, p = r & 3, e = r >> 2;
    g_wtf[t * 4096 + (ks * 64 + n) * 8 + p * 2 + e] = f2tf32(W[i]);
}

// ---------------- pad kernel (slot so ncu -s5 captures conv) ----------------
__global__ void pad_kernel() {}

// ---------------- kernel: conv (mma.sync tf32 single pass) ----------------
#define W_BYTES   (KTAP * 16384)               // 147456
#define SMEM_A    W_BYTES
#define APLANE    32768                         // [8 ks][128 row][8] fp32(tf32)
#define CONV_SMEM (SMEM_A + 2 * APLANE)         // 212992

__global__ void __launch_bounds__(256, 1)
conv_kernel(const float* __restrict__ feats,
            const int* __restrict__ nidx,
            const void* __restrict__ validp,
            int N, int ntiles) {
    extern __shared__ char smem[];
    __shared__ float s_sum[COUT];
    __shared__ float s_ssq[COUT];

    const int tid = threadIdx.x, warp = tid >> 5, lane = tid & 31;
    const int vu8 = g_valid_u8;
    const int* __restrict__ v32 = (const int*)validp;
    const unsigned char* __restrict__ v8 = (const unsigned char*)validp;

    if (tid < COUT) { s_sum[tid] = 0.0f; s_ssq[tid] = 0.0f; }

    // copy W planes into SMEM (visibility covered by first tap __syncthreads)
    {
        const uint4* s = (const uint4*)g_wtf;
        uint4* d = (uint4*)smem;
        for (int i = tid; i < W_BYTES / 16; i += 256) d[i] = s[i];
    }

    // warp tiling: 4 m-slices x 2 n-slices of 32x32
    const int warp_m = warp & 3;
    const int warp_n = warp >> 2;
    // gather mapping: 2 threads per row
    const int rit  = tid >> 1;
    const int half = tid & 1;
    // lane-constant byte offsets
    const uint32_t aoff = (uint32_t)(warp_m * 32 * 32 + (lane >> 2) * 32 +
                                     (lane & 3) * 8);
    const uint32_t woff = (uint32_t)((warp_n * 32 + (lane >> 2)) * 32 +
                                     (lane & 3) * 8);

    // gather state (one tap ahead)
    int gtile = blockIdx.x, gtap = 0;
    float4 f[8];
    auto do_gather = [&]() {
        const int r = gtile * TILE_M + rit;
        bool live = false;
        const float4* src = nullptr;
        if (r < N) {
            const int vidx = r * KTAP + gtap;
            const bool v = vu8 ? (v8[vidx] != 0) : (v32[vidx] != 0);
            if (v) {
                live = true;
                src = (const float4*)(feats + (size_t)nidx[vidx] * CIN + half * 32);
            }
        }
        if (live) {
            #pragma unroll
            for (int j = 0; j < 8; j++) f[j] = src[j];
        } else {
            #pragma unroll
            for (int j = 0; j < 8; j++) f[j] = make_float4(0.f, 0.f, 0.f, 0.f);
        }
    };
    if (gtile < ntiles) do_gather();

    float st_sum[8], st_ssq[8];
    #pragma unroll
    for (int i = 0; i < 8; i++) { st_sum[i] = 0.f; st_ssq[i] = 0.f; }

    int parity = 0;

    for (int tile = blockIdx.x; tile < ntiles; tile += gridDim.x) {
        float C[2][4][4];
        #pragma unroll
        for (int mb = 0; mb < 2; mb++)
            #pragma unroll
            for (int nb = 0; nb < 4; nb++)
                #pragma unroll
                for (int q = 0; q < 4; q++) C[mb][nb][q] = 0.f;

        for (int tap = 0; tap < KTAP; tap++) {
            // ---- stage gathered rows as tf32, k-pair-interleaved ----
            // A_s[ks][row][p*2+e], k = half*32 + j4*4 + e2
            char* abuf = smem + SMEM_A + parity * APLANE;
            #pragma unroll
            for (int j4 = 0; j4 < 8; j4++) {
                float v0 = f[j4].x, v1 = f[j4].y, v2 = f[j4].z, v3 = f[j4].w;
                #pragma unroll
                for (int e2 = 0; e2 < 4; e2++) {
                    const int q = j4 * 4 + e2;
                    const int ks = (half << 2) + (q >> 3);
                    const int r = q & 7;
                    const int off = ks * 4096 + rit * 32 + (r & 3) * 8 + (r >> 2) * 4;
                    float v = (e2 == 0) ? v0 : (e2 == 1) ? v1 : (e2 == 2) ? v2 : v3;
                    *(uint32_t*)(abuf + off) = f2tf32(v);
                }
            }
            __syncthreads();

            // ---- issue next gather (LDGs overlap the MMA block below) ----
            if (++gtap == KTAP) { gtap = 0; gtile += gridDim.x; }
            if (gtile < ntiles) do_gather();

            // ---- MMA: tf32 single pass ----
            const char* wbase = smem + tap * 16384;
            const char* abase = smem + SMEM_A + parity * APLANE;
            #pragma unroll
            for (int ks = 0; ks < 8; ks++) {
                uint2 Wf[4];
                #pragma unroll
                for (int nb = 0; nb < 4; nb++)
                    Wf[nb] = *(const uint2*)(wbase + ks * 2048 + nb * 256 + woff);
                uint2 A02[2], A13[2];
                #pragma unroll
                for (int mb = 0; mb < 2; mb++) {
                    A02[mb] = *(const uint2*)(abase + ks * 4096 + mb * 512 + aoff);
                    A13[mb] = *(const uint2*)(abase + ks * 4096 + mb * 512 + 256 + aoff);
                }
                #pragma unroll
                for (int mb = 0; mb < 2; mb++)
                    #pragma unroll
                    for (int nb = 0; nb < 4; nb++)
                        mma_tf32(C[mb][nb], A02[mb].x, A13[mb].x,
                                 A02[mb].y, A13[mb].y, Wf[nb].x, Wf[nb].y);
            }
            parity ^= 1;
        }

        // ---- epilogue: store y, accumulate BN stats in regs ----
        {
            const int r0 = tile * TILE_M + warp_m * 32 + (lane >> 2);
            const int cbase = warp_n * 32 + (lane & 3) * 2;
            #pragma unroll
            for (int mb = 0; mb < 2; mb++) {
                const int ra = r0 + mb * 16;
                const int rb = ra + 8;
                #pragma unroll
                for (int nb = 0; nb < 4; nb++) {
                    const int c = cbase + nb * 8;
                    if (ra < N)
                        *(float2*)(g_y + (size_t)ra * COUT + c) =
                            make_float2(C[mb][nb][0], C[mb][nb][1]);
                    if (rb < N)
                        *(float2*)(g_y + (size_t)rb * COUT + c) =
                            make_float2(C[mb][nb][2], C[mb][nb][3]);
                    // rows >= N contributed zeros (gather zero-fill) -> no guard
                    st_sum[nb * 2 + 0] += C[mb][nb][0] + C[mb][nb][2];
                    st_sum[nb * 2 + 1] += C[mb][nb][1] + C[mb][nb][3];
                    st_ssq[nb * 2 + 0] += C[mb][nb][0] * C[mb][nb][0] +
                                          C[mb][nb][2] * C[mb][nb][2];
                    st_ssq[nb * 2 + 1] += C[mb][nb][1] * C[mb][nb][1] +
                                          C[mb][nb][3] * C[mb][nb][3];
                }
            }
        }
    }

    // ---- stats: regs -> smem -> global ----
    __syncthreads();
    {
        const int cbase = warp_n * 32 + (lane & 3) * 2;
        #pragma unroll
        for (int nb = 0; nb < 4; nb++) {
            atomicAdd(&s_sum[cbase + nb * 8 + 0], st_sum[nb * 2 + 0]);
            atomicAdd(&s_sum[cbase + nb * 8 + 1], st_sum[nb * 2 + 1]);
            atomicAdd(&s_ssq[cbase + nb * 8 + 0], st_ssq[nb * 2 + 0]);
            atomicAdd(&s_ssq[cbase + nb * 8 + 1], st_ssq[nb * 2 + 1]);
        }
    }
    __syncthreads();
    if (tid < COUT) {
        atomicAdd(&g_sum[tid], s_sum[tid]);
        atomicAdd(&g_ssq[tid], s_ssq[tid]);
    }
}

// ---------------- kernel: finalize BN scale/bias ----------------
__global__ void bn_finalize_kernel(const float* __restrict__ gamma,
                                   const float* __restrict__ beta, int N) {
    int c = threadIdx.x;
    if (c < COUT) {
        float inv_n = 1.0f / (float)N;
        float mean = g_sum[c] * inv_n;
        float var = g_ssq[c] * inv_n - mean * mean;
        float sc = gamma[c] * rsqrtf(var + EPS_BN);
        g_scale[c] = sc;
        g_bias[c] = beta[c] - mean * sc;
    }
}

// ---------------- kernel: apply BN + LeakyReLU ----------------
__global__ void __launch_bounds__(256)
apply_kernel(float* __restrict__ out, int total4) {
    __shared__ float ss[COUT];
    __shared__ float sb_[COUT];
    if (threadIdx.x < COUT) {
        ss[threadIdx.x] = g_scale[threadIdx.x];
        sb_[threadIdx.x] = g_bias[threadIdx.x];
    }
    __syncthreads();
    const float4* y4 = (const float4*)g_y;
    float4* o4 = (float4*)out;
    for (int i = blockIdx.x * blockDim.x + threadIdx.x; i < total4;
         i += gridDim.x * blockDim.x) {
        float4 y = y4[i];
        int c = (i & 15) * 4;
        float4 o;
        o.x = y.x * ss[c + 0] + sb_[c + 0];
        o.y = y.y * ss[c + 1] + sb_[c + 1];
        o.z = y.z * ss[c + 2] + sb_[c + 2];
        o.w = y.w * ss[c + 3] + sb_[c + 3];
        o.x = (o.x >= 0.f) ? o.x : LEAK * o.x;
        o.y = (o.y >= 0.f) ? o.y : LEAK * o.y;
        o.z = (o.z >= 0.f) ? o.z : LEAK * o.z;
        o.w = (o.w >= 0.f) ? o.w : LEAK * o.w;
        o4[i] = o;
    }
}

// ---------------- launch ----------------
extern "C" void kernel_launch(void* const* d_in, const int* in_sizes, int n_in,
                              void* d_out, int out_size) {
    const float* feats = (const float*)d_in[0];
    const float* W     = (const float*)d_in[1];
    const float* gamma = (const float*)d_in[2];
    const float* beta  = (const float*)d_in[3];
    const int*   nidx  = (const int*)d_in[4];
    const void*  valid = (const void*)d_in[5];

    const int N = in_sizes[0] / CIN;
    const int ntiles = (N + TILE_M - 1) / TILE_M;

    cudaFuncSetAttribute(conv_kernel,
                         cudaFuncAttributeMaxDynamicSharedMemorySize, CONV_SMEM);

    init_kernel<<<1, 256>>>((const unsigned int*)valid, 4096);   // launch 1
    prep_w_kernel<<<(KTAP * CIN * COUT + 255) / 256, 256>>>(W);  // launch 2
    pad_kernel<<<1, 32>>>();                                     // launch 3

    int grid = 152;
    if (grid > ntiles) grid = ntiles;
    conv_kernel<<<grid, 256, CONV_SMEM>>>(feats, nidx, valid, N, ntiles); // launch 4

    bn_finalize_kernel<<<1, 64>>>(gamma, beta, N);

    const int total4 = (N * COUT) / 4;
    apply_kernel<<<8192, 256>>>((float*)d_out, total4);
}